// round 2
// baseline (speedup 1.0000x reference)
#include <cuda_runtime.h>
#include <cstdint>

// AnchorLoss: sum over masked pairs of 1 - exp(-||p_i - p_j||^2 / 10),
// p = embedding + abs_coords, B=8, N=2048, D=2.
//
// dist^2 = |pi|^2 + |pj|^2 - 2 pi.pj, and with C = -log2(e)/10:
//   exp(-d2/10) = ex2(C*d2) = ex2(si) * ex2(sj + ax*pix + ay*piy)
// where si = C|pi|^2, sj = C|pj|^2, ax = -2C*pj.x, ay = -2C*pj.y.
// Per-j triple (ax, ay, sj) lives in smem as float4 (one LDS.128),
// transposed so int4-vectorized mask loads line up with 4 conflict-free LDS.

constexpr int BDIM = 8;
constexpr int NDIM = 2048;
constexpr int ROWS = 8;             // i-rows per block (one warp per row)
constexpr int THREADS = ROWS * 32;  // 256
constexpr int GRID_X = NDIM / ROWS;        // 256
constexpr int NBLOCKS = GRID_X * BDIM;     // 2048
constexpr int Q = NDIM / 4;                // 512 (transposed stride)

__device__ float g_partial[NBLOCKS];
__device__ unsigned int g_count = 0;

__device__ __forceinline__ float ex2_approx(float x) {
    float r;
    asm("ex2.approx.ftz.f32 %0, %1;" : "=f"(r) : "f"(x));
    return r;
}

__global__ void __launch_bounds__(THREADS)
anchor_fused(const float* __restrict__ emb,
             const float* __restrict__ coords,
             const int*   __restrict__ mask,
             float*       __restrict__ out) {
    __shared__ float4 sp[NDIM];   // transposed: sp[(j&3)*Q + (j>>2)]
    __shared__ float wsum[ROWS];
    __shared__ unsigned s_ticket;

    constexpr float NEGC = -0.14426950408889634f;   // -log2(e)/10
    constexpr float TWOC =  0.28853900817779268f;   // -2*NEGC

    const int b = blockIdx.y;
    const float2* e2 = reinterpret_cast<const float2*>(emb    + (size_t)b * NDIM * 2);
    const float2* c2 = reinterpret_cast<const float2*>(coords + (size_t)b * NDIM * 2);

    for (int t = threadIdx.x; t < NDIM; t += THREADS) {
        float2 e = e2[t];
        float2 c = c2[t];
        float px = e.x + c.x, py = e.y + c.y;
        sp[(t & 3) * Q + (t >> 2)] =
            make_float4(TWOC * px, TWOC * py, NEGC * fmaf(px, px, py * py), 0.0f);
    }
    __syncthreads();

    const int warp = threadIdx.x >> 5;
    const int lane = threadIdx.x & 31;
    const int i = blockIdx.x * ROWS + warp;

    // row-i point (broadcast load, L2-hit)
    const float2 ei = e2[i], ci = c2[i];
    const float pix = ei.x + ci.x, piy = ei.y + ci.y;
    const float si = NEGC * fmaf(pix, pix, piy * piy);

    const int4* mrow = reinterpret_cast<const int4*>(
        mask + ((size_t)b * NDIM + (size_t)i) * NDIM);

    float accE = 0.0f;  // sum of m * ex2(sj + dot)
    int   cnt  = 0;     // count of m==1

#pragma unroll 4
    for (int it = 0; it < NDIM / 128; ++it) {   // 16 iterations
        const int a = it * 32 + lane;           // int4 index == transposed index
        const int4 m = __ldcs(&mrow[a]);        // masks for j = 4a .. 4a+3

        const float4 q0 = sp[0 * Q + a];
        const float4 q1 = sp[1 * Q + a];
        const float4 q2 = sp[2 * Q + a];
        const float4 q3 = sp[3 * Q + a];

        accE = fmaf((float)m.x, ex2_approx(fmaf(q0.x, pix, fmaf(q0.y, piy, q0.z))), accE);
        accE = fmaf((float)m.y, ex2_approx(fmaf(q1.x, pix, fmaf(q1.y, piy, q1.z))), accE);
        accE = fmaf((float)m.z, ex2_approx(fmaf(q2.x, pix, fmaf(q2.y, piy, q2.z))), accE);
        accE = fmaf((float)m.w, ex2_approx(fmaf(q3.x, pix, fmaf(q3.y, piy, q3.z))), accE);
        cnt += m.x + m.y + m.z + m.w;
    }

    float val = (float)cnt - ex2_approx(si) * accE;

    // warp reduce
#pragma unroll
    for (int off = 16; off; off >>= 1)
        val += __shfl_xor_sync(0xffffffffu, val, off);

    if (lane == 0) wsum[warp] = val;
    __syncthreads();

    if (threadIdx.x == 0) {
        float s = 0.0f;
#pragma unroll
        for (int w = 0; w < ROWS; ++w) s += wsum[w];
        g_partial[blockIdx.y * GRID_X + blockIdx.x] = s;
        __threadfence();
        s_ticket = atomicAdd(&g_count, 1u);
    }
    __syncthreads();

    // Last block to finish performs the deterministic final reduction.
    if (s_ticket == NBLOCKS - 1) {
        __threadfence();  // acquire: make all g_partial writes visible
        double* sd = reinterpret_cast<double*>(sp);  // reuse smem (done with sp)
        double acc = 0.0;
        for (int idx = threadIdx.x; idx < NBLOCKS; idx += THREADS)
            acc += (double)g_partial[idx];
        sd[threadIdx.x] = acc;
        __syncthreads();
#pragma unroll
        for (int off = THREADS / 2; off; off >>= 1) {
            if (threadIdx.x < off) sd[threadIdx.x] += sd[threadIdx.x + off];
            __syncthreads();
        }
        if (threadIdx.x == 0) {
            out[0] = (float)sd[0];
            g_count = 0;   // reset for next graph replay
        }
    }
}

extern "C" void kernel_launch(void* const* d_in, const int* in_sizes, int n_in,
                              void* d_out, int out_size) {
    const float* emb    = (const float*)d_in[0];
    const float* coords = (const float*)d_in[1];
    const int*   mask   = (const int*)d_in[2];
    float* out = (float*)d_out;

    dim3 grid(GRID_X, BDIM);
    anchor_fused<<<grid, THREADS>>>(emb, coords, mask, out);
}

// round 3
// speedup vs baseline: 1.1221x; 1.1221x over previous
#include <cuda_runtime.h>
#include <cstdint>

// AnchorLoss: sum over masked pairs of 1 - exp(-||p_i - p_j||^2 / 10),
// p = embedding + abs_coords, B=8, N=2048, D=2.
//
// Factored form: with C = -log2(e)/10,
//   exp(-d2/10) = ex2(C*|pi|^2) * ex2( (C|pj|^2) + (-2C pj.x)*pi.x + (-2C pj.y)*pi.y )
// Per-j triple (ax, ay, sj) in smem as float4 (one LDS.128), transposed so
// int4 mask loads line up with conflict-free LDS. Each warp handles TWO
// i-rows, reusing each smem load for both rows (8 B smem / pair) and
// doubling mask-stream MLP.

constexpr int BDIM = 8;
constexpr int NDIM = 2048;
constexpr int WARPS = 8;
constexpr int THREADS = WARPS * 32;        // 256
constexpr int ROWS_BLK = WARPS * 2;        // 16 i-rows per block
constexpr int GRID_X = NDIM / ROWS_BLK;    // 128
constexpr int NBLOCKS = GRID_X * BDIM;     // 1024
constexpr int Q = NDIM / 4;                // 512 (transposed stride)

__device__ float g_partial[NBLOCKS];
__device__ unsigned int g_count = 0;

__device__ __forceinline__ float ex2_approx(float x) {
    float r;
    asm("ex2.approx.ftz.f32 %0, %1;" : "=f"(r) : "f"(x));
    return r;
}

__global__ void __launch_bounds__(THREADS)
anchor_fused(const float* __restrict__ emb,
             const float* __restrict__ coords,
             const int*   __restrict__ mask,
             float*       __restrict__ out) {
    __shared__ float4 sp[NDIM];   // transposed: sp[(j&3)*Q + (j>>2)] = (ax, ay, sj, 0)
    __shared__ float wsum[WARPS];
    __shared__ unsigned s_ticket;

    constexpr float NEGC = -0.14426950408889634f;   // -log2(e)/10
    constexpr float TWOC =  0.28853900817779268f;   // -2*NEGC

    const int b = blockIdx.y;
    const float2* e2 = reinterpret_cast<const float2*>(emb    + (size_t)b * NDIM * 2);
    const float2* c2 = reinterpret_cast<const float2*>(coords + (size_t)b * NDIM * 2);

    for (int t = threadIdx.x; t < NDIM; t += THREADS) {
        float2 e = e2[t];
        float2 c = c2[t];
        float px = e.x + c.x, py = e.y + c.y;
        sp[(t & 3) * Q + (t >> 2)] =
            make_float4(TWOC * px, TWOC * py, NEGC * fmaf(px, px, py * py), 0.0f);
    }
    __syncthreads();

    const int warp = threadIdx.x >> 5;
    const int lane = threadIdx.x & 31;
    const int i0 = blockIdx.x * ROWS_BLK + warp * 2;
    const int i1 = i0 + 1;

    // row points (L2-hit broadcast loads)
    float2 ea = e2[i0], ca = c2[i0];
    float2 eb = e2[i1], cb = c2[i1];
    const float pax = ea.x + ca.x, pay = ea.y + ca.y;
    const float pbx = eb.x + cb.x, pby = eb.y + cb.y;
    const float sa = NEGC * fmaf(pax, pax, pay * pay);
    const float sb = NEGC * fmaf(pbx, pbx, pby * pby);

    const int4* mrow0 = reinterpret_cast<const int4*>(
        mask + ((size_t)b * NDIM + (size_t)i0) * NDIM);
    const int4* mrow1 = reinterpret_cast<const int4*>(
        mask + ((size_t)b * NDIM + (size_t)i1) * NDIM);

    float accA = 0.0f, accB = 0.0f;
    int   cntA = 0,    cntB = 0;

#pragma unroll 2
    for (int it = 0; it < NDIM / 128; ++it) {   // 16 iterations
        const int a = it * 32 + lane;           // int4 index == transposed index
        const int4 m0 = __ldcs(&mrow0[a]);      // masks for row i0, j = 4a..4a+3
        const int4 m1 = __ldcs(&mrow1[a]);      // masks for row i1

        const float4 q0 = sp[0 * Q + a];
        const float4 q1 = sp[1 * Q + a];
        const float4 q2 = sp[2 * Q + a];
        const float4 q3 = sp[3 * Q + a];

#define PAIR(qc, mc0, mc1)                                                     \
        {                                                                      \
            float eA = ex2_approx(fmaf(qc.x, pax, fmaf(qc.y, pay, qc.z)));     \
            float eB = ex2_approx(fmaf(qc.x, pbx, fmaf(qc.y, pby, qc.z)));     \
            accA += __int_as_float(__float_as_int(eA) & -(mc0));               \
            accB += __int_as_float(__float_as_int(eB) & -(mc1));               \
            cntA += (mc0);                                                     \
            cntB += (mc1);                                                     \
        }
        PAIR(q0, m0.x, m1.x)
        PAIR(q1, m0.y, m1.y)
        PAIR(q2, m0.z, m1.z)
        PAIR(q3, m0.w, m1.w)
#undef PAIR
    }

    float val = ((float)cntA - ex2_approx(sa) * accA)
              + ((float)cntB - ex2_approx(sb) * accB);

    // warp reduce
#pragma unroll
    for (int off = 16; off; off >>= 1)
        val += __shfl_xor_sync(0xffffffffu, val, off);

    if (lane == 0) wsum[warp] = val;
    __syncthreads();

    if (threadIdx.x == 0) {
        float s = 0.0f;
#pragma unroll
        for (int w = 0; w < WARPS; ++w) s += wsum[w];
        g_partial[blockIdx.y * GRID_X + blockIdx.x] = s;
        __threadfence();
        s_ticket = atomicAdd(&g_count, 1u);
    }
    __syncthreads();

    // Last block performs the deterministic final reduction.
    if (s_ticket == NBLOCKS - 1) {
        __threadfence();  // make all g_partial writes visible
        double* sd = reinterpret_cast<double*>(sp);  // reuse smem
        double acc = 0.0;
        for (int idx = threadIdx.x; idx < NBLOCKS; idx += THREADS)
            acc += (double)g_partial[idx];
        sd[threadIdx.x] = acc;
        __syncthreads();
#pragma unroll
        for (int off = THREADS / 2; off; off >>= 1) {
            if (threadIdx.x < off) sd[threadIdx.x] += sd[threadIdx.x + off];
            __syncthreads();
        }
        if (threadIdx.x == 0) {
            out[0] = (float)sd[0];
            g_count = 0;   // reset for next graph replay
        }
    }
}

extern "C" void kernel_launch(void* const* d_in, const int* in_sizes, int n_in,
                              void* d_out, int out_size) {
    const float* emb    = (const float*)d_in[0];
    const float* coords = (const float*)d_in[1];
    const int*   mask   = (const int*)d_in[2];
    float* out = (float*)d_out;

    dim3 grid(GRID_X, BDIM);
    anchor_fused<<<grid, THREADS>>>(emb, coords, mask, out);
}

// round 4
// speedup vs baseline: 1.2869x; 1.1468x over previous
#include <cuda_runtime.h>
#include <cstdint>

// AnchorLoss: sum over masked pairs of 1 - exp(-||p_i - p_j||^2 / 10),
// p = embedding + abs_coords, B=8, N=2048, D=2.
//
// R1-proven shape: float2 smem point cache (16KB -> 8 blocks/SM, 64 warps
// resident; occupancy is the measured BW lever), 1 i-row per warp, int4
// mask loads with transposed smem so LDS is conflict-free. Fused final
// reduction via ticket counter; bitwise gating instead of I2F.

constexpr int BDIM = 8;
constexpr int NDIM = 2048;
constexpr int ROWS = 8;             // i-rows per block (one warp per row)
constexpr int THREADS = ROWS * 32;  // 256
constexpr int GRID_X = NDIM / ROWS;        // 256
constexpr int NBLOCKS = GRID_X * BDIM;     // 2048
constexpr int Q = NDIM / 4;                // 512 (transposed stride)

__device__ float g_partial[NBLOCKS];
__device__ unsigned int g_count = 0;

__device__ __forceinline__ float ex2_approx(float x) {
    float r;
    asm("ex2.approx.ftz.f32 %0, %1;" : "=f"(r) : "f"(x));
    return r;
}

__global__ void __launch_bounds__(THREADS, 8)
anchor_fused(const float* __restrict__ emb,
             const float* __restrict__ coords,
             const int*   __restrict__ mask,
             float*       __restrict__ out) {
    // Transposed point cache: sp[(j&3)*Q + (j>>2)] = p[j]   (16 KB)
    __shared__ float2 sp[NDIM];
    __shared__ float wsum[ROWS];
    __shared__ unsigned s_ticket;

    constexpr float NEGC = -0.14426950408889634f;  // -log2(e)/10

    const int b = blockIdx.y;
    const float2* e2 = reinterpret_cast<const float2*>(emb    + (size_t)b * NDIM * 2);
    const float2* c2 = reinterpret_cast<const float2*>(coords + (size_t)b * NDIM * 2);

    for (int t = threadIdx.x; t < NDIM; t += THREADS) {
        float2 e = e2[t];
        float2 c = c2[t];
        sp[(t & 3) * Q + (t >> 2)] = make_float2(e.x + c.x, e.y + c.y);
    }
    __syncthreads();

    const int warp = threadIdx.x >> 5;
    const int lane = threadIdx.x & 31;
    const int i = blockIdx.x * ROWS + warp;

    const float2 pi = sp[(i & 3) * Q + (i >> 2)];
    const int4* mrow = reinterpret_cast<const int4*>(
        mask + ((size_t)b * NDIM + (size_t)i) * NDIM);

    float accE = 0.0f;  // sum of m * exp(...)
    int   cnt  = 0;     // count of m==1

#pragma unroll 4
    for (int it = 0; it < NDIM / 128; ++it) {   // 16 iterations
        const int a = it * 32 + lane;           // int4 index == transposed index
        const int4 m = __ldcs(&mrow[a]);        // masks for j = 4a .. 4a+3

        const float2 p0 = sp[0 * Q + a];
        const float2 p1 = sp[1 * Q + a];
        const float2 p2 = sp[2 * Q + a];
        const float2 p3 = sp[3 * Q + a];

#define PAIR(pc, mc)                                                       \
        {                                                                  \
            float dx = pi.x - pc.x, dy = pi.y - pc.y;                      \
            float e = ex2_approx(fmaf(dy, dy, dx * dx) * NEGC);            \
            accE += __int_as_float(__float_as_int(e) & -(mc));             \
            cnt += (mc);                                                   \
        }
        PAIR(p0, m.x)
        PAIR(p1, m.y)
        PAIR(p2, m.z)
        PAIR(p3, m.w)
#undef PAIR
    }

    float val = (float)cnt - accE;

    // warp reduce
#pragma unroll
    for (int off = 16; off; off >>= 1)
        val += __shfl_xor_sync(0xffffffffu, val, off);

    if (lane == 0) wsum[warp] = val;
    __syncthreads();

    if (threadIdx.x == 0) {
        float s = 0.0f;
#pragma unroll
        for (int w = 0; w < ROWS; ++w) s += wsum[w];
        g_partial[blockIdx.y * GRID_X + blockIdx.x] = s;
        __threadfence();
        s_ticket = atomicAdd(&g_count, 1u);
    }
    __syncthreads();

    // Last block performs the deterministic final reduction.
    if (s_ticket == NBLOCKS - 1) {
        __threadfence();  // make all g_partial writes visible
        double* sd = reinterpret_cast<double*>(sp);  // reuse smem
        double acc = 0.0;
        for (int idx = threadIdx.x; idx < NBLOCKS; idx += THREADS)
            acc += (double)g_partial[idx];
        sd[threadIdx.x] = acc;
        __syncthreads();
#pragma unroll
        for (int off = THREADS / 2; off; off >>= 1) {
            if (threadIdx.x < off) sd[threadIdx.x] += sd[threadIdx.x + off];
            __syncthreads();
        }
        if (threadIdx.x == 0) {
            out[0] = (float)sd[0];
            g_count = 0;   // reset for next graph replay
        }
    }
}

extern "C" void kernel_launch(void* const* d_in, const int* in_sizes, int n_in,
                              void* d_out, int out_size) {
    const float* emb    = (const float*)d_in[0];
    const float* coords = (const float*)d_in[1];
    const int*   mask   = (const int*)d_in[2];
    float* out = (float*)d_out;

    dim3 grid(GRID_X, BDIM);
    anchor_fused<<<grid, THREADS>>>(emb, coords, mask, out);
}

// round 5
// speedup vs baseline: 1.3068x; 1.0154x over previous
#include <cuda_runtime.h>
#include <cstdint>

// AnchorLoss: sum over masked pairs of 1 - exp(-||p_i - p_j||^2 / 10),
// p = embedding + abs_coords, B=8, N=2048, D=2.
//
// Shape (measured-best): float2 smem point cache (16KB -> 8 blocks/SM,
// 64 warps), 1 i-row per warp, int4 mask loads. This round: explicit
// distance-1 mask prefetch (decouple LDG latency from the compute chain)
// and linear smem layout so each mask int4 pairs with two LDS.128.

constexpr int BDIM = 8;
constexpr int NDIM = 2048;
constexpr int ROWS = 8;             // i-rows per block (one warp per row)
constexpr int THREADS = ROWS * 32;  // 256
constexpr int GRID_X = NDIM / ROWS;        // 256
constexpr int NBLOCKS = GRID_X * BDIM;     // 2048
constexpr int NITER = NDIM / 128;          // 16 int4-columns per lane

__device__ float g_partial[NBLOCKS];
__device__ unsigned int g_count = 0;

__device__ __forceinline__ float ex2_approx(float x) {
    float r;
    asm("ex2.approx.ftz.f32 %0, %1;" : "=f"(r) : "f"(x));
    return r;
}

__global__ void __launch_bounds__(THREADS, 8)
anchor_fused(const float* __restrict__ emb,
             const float* __restrict__ coords,
             const int*   __restrict__ mask,
             float*       __restrict__ out) {
    __shared__ float2 sp[NDIM];   // linear: sp[j] = p[j]  (16 KB)
    __shared__ float wsum[ROWS];
    __shared__ unsigned s_ticket;

    constexpr float NEGC = -0.14426950408889634f;  // -log2(e)/10

    const int b = blockIdx.y;
    const float2* e2 = reinterpret_cast<const float2*>(emb    + (size_t)b * NDIM * 2);
    const float2* c2 = reinterpret_cast<const float2*>(coords + (size_t)b * NDIM * 2);

    for (int t = threadIdx.x; t < NDIM; t += THREADS) {
        float2 e = e2[t];
        float2 c = c2[t];
        sp[t] = make_float2(e.x + c.x, e.y + c.y);
    }
    __syncthreads();

    const int warp = threadIdx.x >> 5;
    const int lane = threadIdx.x & 31;
    const int i = blockIdx.x * ROWS + warp;

    const float2 pi = sp[i];
    const int4* mrow = reinterpret_cast<const int4*>(
        mask + ((size_t)b * NDIM + (size_t)i) * NDIM);
    const float4* spv = reinterpret_cast<const float4*>(sp);

    float accE = 0.0f;  // sum of m * exp(...)
    int   cnt  = 0;     // count of m==1

    auto body = [&](int4 m, int a) {
        // points j = 4a .. 4a+3 : two contiguous float4 = four float2
        const float4 v01 = spv[2 * a + 0];
        const float4 v23 = spv[2 * a + 1];
#define PAIR(px_, py_, mc)                                                 \
        {                                                                  \
            float dx = pi.x - (px_), dy = pi.y - (py_);                    \
            float e = ex2_approx(fmaf(dy, dy, dx * dx) * NEGC);            \
            accE += __int_as_float(__float_as_int(e) & -(mc));             \
            cnt += (mc);                                                   \
        }
        PAIR(v01.x, v01.y, m.x)
        PAIR(v01.z, v01.w, m.y)
        PAIR(v23.x, v23.y, m.z)
        PAIR(v23.z, v23.w, m.w)
#undef PAIR
    };

    // Distance-1 prefetch: LDG for iteration it+1 issues before compute(it).
    int4 mcur = __ldcs(&mrow[lane]);
#pragma unroll 5
    for (int it = 0; it < NITER - 1; ++it) {
        int4 mnext = __ldcs(&mrow[(it + 1) * 32 + lane]);
        body(mcur, it * 32 + lane);
        mcur = mnext;
    }
    body(mcur, (NITER - 1) * 32 + lane);

    float val = (float)cnt - accE;

    // warp reduce
#pragma unroll
    for (int off = 16; off; off >>= 1)
        val += __shfl_xor_sync(0xffffffffu, val, off);

    if (lane == 0) wsum[warp] = val;
    __syncthreads();

    if (threadIdx.x == 0) {
        float s = 0.0f;
#pragma unroll
        for (int w = 0; w < ROWS; ++w) s += wsum[w];
        g_partial[blockIdx.y * GRID_X + blockIdx.x] = s;
        __threadfence();
        s_ticket = atomicAdd(&g_count, 1u);
    }
    __syncthreads();

    // Last block performs the deterministic final reduction.
    if (s_ticket == NBLOCKS - 1) {
        __threadfence();  // make all g_partial writes visible
        double* sd = reinterpret_cast<double*>(sp);  // reuse smem
        double acc = 0.0;
        for (int idx = threadIdx.x; idx < NBLOCKS; idx += THREADS)
            acc += (double)g_partial[idx];
        sd[threadIdx.x] = acc;
        __syncthreads();
#pragma unroll
        for (int off = THREADS / 2; off; off >>= 1) {
            if (threadIdx.x < off) sd[threadIdx.x] += sd[threadIdx.x + off];
            __syncthreads();
        }
        if (threadIdx.x == 0) {
            out[0] = (float)sd[0];
            g_count = 0;   // reset for next graph replay
        }
    }
}

extern "C" void kernel_launch(void* const* d_in, const int* in_sizes, int n_in,
                              void* d_out, int out_size) {
    const float* emb    = (const float*)d_in[0];
    const float* coords = (const float*)d_in[1];
    const int*   mask   = (const int*)d_in[2];
    float* out = (float*)d_out;

    dim3 grid(GRID_X, BDIM);
    anchor_fused<<<grid, THREADS>>>(emb, coords, mask, out);
}